// round 12
// baseline (speedup 1.0000x reference)
#include <cuda_runtime.h>
#include <math.h>
#include <stdint.h>

#define L_SEQ   600
#define BATCH   64
#define DSPEC   552
#define DPRE    256
#define DH      1024
#define G4      4096
#define MROWS   (L_SEQ*BATCH)   // 38400
#define NBLK    128

// conv pack geometry
#define CP_SZ1  (8*18*5*2048)
#define CP_SZ2  (8*16*5*2048)
#define CP_SZ5  (9*16*5*2048)
#define CP_OFF1 0
#define CP_OFF2 (CP_OFF1 + CP_SZ1)
#define CP_OFF3 (CP_OFF2 + CP_SZ2)
#define CP_OFF4 (CP_OFF3 + CP_SZ2)
#define CP_OFF5 (CP_OFF4 + CP_SZ2)
#define CP_TOT  (CP_OFF5 + CP_SZ5)

// gemm_tc pack sizes
#define GP_SZ_W0 (64*8*2048)      // Wih0: N=4096, K=256
#define GP_SZ_LN (9*32*2048)      // lin_W: N=552, K=1024
#define GP_SZ_P1 (4*18*2048)      // pre_W1: N=256, K=552 (18 chunks)
#define GP_SZ_P2 (4*8*2048)       // pre_W2: N=256, K=256
#define WP0_SZ   (128*32*1024)
#define WP1_SZ   ((size_t)128*64*1024)

// ---------------- static device scratch ----------------
static __device__ float g_pre1 [(size_t)MROWS*DPRE];
static __device__ float g_pre2 [(size_t)MROWS*DPRE];
static __device__ float g_g0xT [(size_t)L_SEQ*G4*BATCH];     // [t][gate_row][b]
static __device__ float g_wp0  [(size_t)WP0_SZ];
static __device__ float g_wp1  [(size_t)WP1_SZ];
static __device__ float g_cwhi [(size_t)CP_TOT];
static __device__ float g_cwlo [(size_t)CP_TOT];
static __device__ float g_wg0hi[(size_t)GP_SZ_W0];
static __device__ float g_wg0lo[(size_t)GP_SZ_W0];
static __device__ float g_wlnhi[(size_t)GP_SZ_LN];
static __device__ float g_wlnlo[(size_t)GP_SZ_LN];
static __device__ float g_wp1hi[(size_t)GP_SZ_P1];
static __device__ float g_wp1lo[(size_t)GP_SZ_P1];
static __device__ float g_wp2hi[(size_t)GP_SZ_P2];
static __device__ float g_wp2lo[(size_t)GP_SZ_P2];
static __device__ float g_ht0  [2][DH*BATCH];
static __device__ float g_ht1  [2][DH*BATCH];
static __device__ float g_outs [(size_t)L_SEQ*DH*BATCH];     // [t][jj][b]
static __device__ float g_spred[(size_t)BATCH*DSPEC*L_SEQ];  // [B][552][600]
static __device__ float g_cbA  [(size_t)BATCH*DSPEC*L_SEQ];
static __device__ float g_cbB  [(size_t)BATCH*DSPEC*L_SEQ];
static __device__ unsigned int g_ctrA[32];
static __device__ unsigned int g_ctrB[32];

__device__ __forceinline__ float sigmoidf_(float x) { return 1.0f / (1.0f + __expf(-x)); }

__device__ __forceinline__ float tf32r(float x) {
    unsigned u; asm("cvt.rna.tf32.f32 %0, %1;" : "=r"(u) : "f"(x));
    return __uint_as_float(u);
}

__device__ __forceinline__ void cpasync16(void* dst_smem, const void* src) {
    unsigned s = (unsigned)__cvta_generic_to_shared(dst_smem);
    asm volatile("cp.async.cg.shared.global [%0], [%1], 16;" :: "r"(s), "l"(src));
}
__device__ __forceinline__ void cp_commit() {
    asm volatile("cp.async.commit_group;" ::: "memory");
}
__device__ __forceinline__ void cp_wait2() {
    asm volatile("cp.async.wait_group 2;" ::: "memory");
}
__device__ __forceinline__ void cp_wait0() {
    asm volatile("cp.async.wait_group 0;" ::: "memory");
}

__device__ __forceinline__ void mma_tf32(float& d0, float& d1, float& d2, float& d3,
                                         uint4 a, unsigned b0, unsigned b1) {
    asm volatile(
        "mma.sync.aligned.m16n8k8.row.col.f32.tf32.tf32.f32 "
        "{%0,%1,%2,%3}, {%4,%5,%6,%7}, {%8,%9}, {%0,%1,%2,%3};"
        : "+f"(d0), "+f"(d1), "+f"(d2), "+f"(d3)
        : "r"(a.x), "r"(a.y), "r"(a.z), "r"(a.w), "r"(b0), "r"(b1));
}

// ---------------- gemm weight pack helper ----------------
__device__ __forceinline__ void pack_gemm_elem(const float* __restrict__ w,
                                               float* __restrict__ whi,
                                               float* __restrict__ wlo,
                                               int Nrows, int K, int wstride,
                                               int chunks, int i)
{
    int reg = i & 3, lane = (i >> 2) & 31, kc = (i >> 7) & 3, mh = (i >> 9) & 3;
    int rest = i >> 11;
    int c = rest % chunks;
    int ct = rest / chunks;
    int row16 = (lane >> 2) + (reg & 1) * 8;
    int col8  = (lane & 3) + ((reg >> 1) & 1) * 4;
    int n = ct * 64 + mh * 16 + row16;
    int k = c * 32 + kc * 8 + col8;
    float v = (n < Nrows && k < K) ? w[(size_t)n * wstride + k] : 0.f;
    float hi = tf32r(v);
    whi[i] = hi;
    wlo[i] = tf32r(v - hi);
}

__global__ void pack_gemm(const float* __restrict__ w, float* __restrict__ whi,
                          float* __restrict__ wlo, int Nrows, int K, int wstride,
                          int chunks, int elems)
{
    int i = blockIdx.x * blockDim.x + threadIdx.x;
    if (i < elems) pack_gemm_elem(w, whi, wlo, Nrows, K, wstride, chunks, i);
}

// ---------------- fused pack 1: wp0 + lin_W pack + init ----------------
__global__ void pack_w0_fused(const float* __restrict__ Whh0,
                              const float* __restrict__ lin_W,
                              float* __restrict__ wp,
                              float* __restrict__ wlnhi, float* __restrict__ wlnlo)
{
    size_t i = (size_t)blockIdx.x * blockDim.x + threadIdx.x;
    if (i < DH * BATCH) { g_ht0[0][i] = 0.f; g_ht1[0][i] = 0.f; }
    if (i == 0) { g_ctrA[0] = 0u; g_ctrB[0] = 0u; }

    if (i < (size_t)WP0_SZ) {
        int ii = (int)i;
        int reg = ii & 3, lane = (ii >> 2) & 31, kc = (ii >> 7) & 3, mh = (ii >> 9) & 1;
        int chunk = (ii >> 10) & 31, blk = ii >> 15;
        int row16 = (lane >> 2) + (reg & 1) * 8;
        int col8  = (lane & 3) + ((reg >> 1) & 1) * 4;
        int m = mh * 16 + row16;
        int j = (m >> 3) * 1024 + blk * 8 + (m & 7);
        int k = chunk * 32 + kc * 8 + col8;
        wp[ii] = tf32r(Whh0[(size_t)j * 1024 + k]);
    } else {
        int j = (int)(i - WP0_SZ);
        if (j < GP_SZ_LN)
            pack_gemm_elem(lin_W, wlnhi, wlnlo, DSPEC, DH, DH + 128, 32, j);
    }
}

// ---------------- fused pack 2: wp1 + Wih0 pack ----------------
__global__ void pack_w1_fused(const float* __restrict__ Wih1, const float* __restrict__ Whh1,
                              const float* __restrict__ Wih0,
                              float* __restrict__ wp,
                              float* __restrict__ wg0hi, float* __restrict__ wg0lo)
{
    size_t i = (size_t)blockIdx.x * blockDim.x + threadIdx.x;
    if (i < WP1_SZ) {
        int ii = (int)i;
        int reg = ii & 3, lane = (ii >> 2) & 31, kc = (ii >> 7) & 3, mh = (ii >> 9) & 1;
        int chunk = (ii >> 10) & 63, blk = ii >> 16;
        int row16 = (lane >> 2) + (reg & 1) * 8;
        int col8  = (lane & 3) + ((reg >> 1) & 1) * 4;
        int m = mh * 16 + row16;
        int j = (m >> 3) * 1024 + blk * 8 + (m & 7);
        int k = chunk * 32 + kc * 8 + col8;
        float v = (k < 1024) ? Wih1[(size_t)j * 1024 + k] : Whh1[(size_t)j * 1024 + (k - 1024)];
        wp[ii] = tf32r(v);
    } else {
        int j = (int)(i - WP1_SZ);
        if (j < GP_SZ_W0)
            pack_gemm_elem(Wih0, wg0hi, wg0lo, G4, DPRE, DPRE + 128, 8, j);
    }
}

// ---------------- conv weight pack ----------------
__global__ void pack_conv(const float* __restrict__ w, float* __restrict__ whi,
                          float* __restrict__ wlo, int Cout, int Cin, int chunks, int elems)
{
    int i = blockIdx.x * blockDim.x + threadIdx.x;
    if (i >= elems) return;
    int reg = i & 3, lane = (i >> 2) & 31, kc = (i >> 7) & 3, mh = (i >> 9) & 3;
    int rest = i >> 11;
    int tap = rest % 5; rest /= 5;
    int c = rest % chunks;
    int ct = rest / chunks;
    int row16 = (lane >> 2) + (reg & 1) * 8;
    int col8  = (lane & 3) + ((reg >> 1) & 1) * 4;
    int co = ct * 64 + mh * 16 + row16;
    int ci = c * 32 + kc * 8 + col8;
    float v = (co < Cout && ci < Cin) ? w[((size_t)co * Cin + ci) * 5 + tap] : 0.f;
    float hi = tf32r(v);
    whi[i] = hi;
    wlo[i] = tf32r(v - hi);
}

// ---------------- tf32 3x GEMM ----------------
// a_mode 0: A row-major [m][K] (K = row stride), with a_shift (teacher forcing)
//           and Kvalid guard (zero-fill K tail / negative rows).
// a_mode 2: A = [t][k][64].
// c_mode 0: C[(m0+b)*Nout + n] (+relu if act); 1: [B][N][600]; 2: [t][4096][64].
__global__ __launch_bounds__(256, 2)
void gemm_tc(const float* __restrict__ A, const float* __restrict__ whi,
             const float* __restrict__ wlo, const float* __restrict__ b1,
             const float* __restrict__ b2, float* __restrict__ C,
             int K, int chunks, int Nout, int a_mode, int c_mode,
             int a_shift, int Kvalid, int act)
{
    __shared__ float sxh[32][72];
    __shared__ float sxl[32][72];
    int tb = blockIdx.x;
    int ct = blockIdx.y;
    int m0 = tb * 64;
    int tid = threadIdx.x;
    int lane = tid & 31, wid = tid >> 5;
    int mg = wid & 3, ng = wid >> 2;

    float accA[4][4], accB[4][4];
#pragma unroll
    for (int f = 0; f < 4; f++)
#pragma unroll
        for (int r = 0; r < 4; r++) { accA[f][r] = 0.f; accB[f][r] = 0.f; }

    const float* wh_base = whi + (size_t)ct * chunks * 2048 + (mg * 4) * 128 + lane * 4;
    const float* wl_base = wlo + (size_t)ct * chunks * 2048 + (mg * 4) * 128 + lane * 4;

    for (int c = 0; c < chunks; c++) {
        __syncthreads();
        if (a_mode == 0) {
#pragma unroll
            for (int q = 0; q < 2; q++) {
                int idx = q * 256 + tid;
                int m = idx >> 3, kq = idx & 7;
                int row = m0 + m - (a_shift ? 64 : 0);
                int gk = c * 32 + kq * 4;
                float4 v = make_float4(0.f, 0.f, 0.f, 0.f);
                if (row >= 0) {
                    const float* p = A + (size_t)row * K + gk;
                    if (gk + 4 <= Kvalid) v = *(const float4*)p;
                    else {
                        if (gk + 0 < Kvalid) v.x = p[0];
                        if (gk + 1 < Kvalid) v.y = p[1];
                        if (gk + 2 < Kvalid) v.z = p[2];
                        if (gk + 3 < Kvalid) v.w = p[3];
                    }
                }
                float h0 = tf32r(v.x), h1 = tf32r(v.y), h2 = tf32r(v.z), h3 = tf32r(v.w);
                sxh[kq*4+0][m] = h0; sxl[kq*4+0][m] = tf32r(v.x - h0);
                sxh[kq*4+1][m] = h1; sxl[kq*4+1][m] = tf32r(v.y - h1);
                sxh[kq*4+2][m] = h2; sxl[kq*4+2][m] = tf32r(v.z - h2);
                sxh[kq*4+3][m] = h3; sxl[kq*4+3][m] = tf32r(v.w - h3);
            }
        } else {
#pragma unroll
            for (int q = 0; q < 2; q++) {
                int idx = q * 256 + tid;
                int k = idx >> 4, m4 = (idx & 15) * 4;
                float4 v = *(const float4*)(A + ((size_t)tb * K + c * 32 + k) * 64 + m4);
                float h0 = tf32r(v.x), h1 = tf32r(v.y), h2 = tf32r(v.z), h3 = tf32r(v.w);
                sxh[k][m4+0] = h0; sxl[k][m4+0] = tf32r(v.x - h0);
                sxh[k][m4+1] = h1; sxl[k][m4+1] = tf32r(v.y - h1);
                sxh[k][m4+2] = h2; sxl[k][m4+2] = tf32r(v.z - h2);
                sxh[k][m4+3] = h3; sxl[k][m4+3] = tf32r(v.w - h3);
            }
        }
        __syncthreads();
        const float* whp = wh_base + (size_t)c * 2048;
        const float* wlp = wl_base + (size_t)c * 2048;
        uint4 ah[4], al[4];
#pragma unroll
        for (int kc = 0; kc < 4; kc++) {
            ah[kc] = *(const uint4*)(whp + kc * 128);
            al[kc] = *(const uint4*)(wlp + kc * 128);
        }
#pragma unroll
        for (int kc = 0; kc < 4; kc++) {
            int krow = kc * 8 + (lane & 3);
#pragma unroll
            for (int f = 0; f < 4; f++) {
                int lcol = ng * 32 + f * 8 + (lane >> 2);
                unsigned bh0 = __float_as_uint(sxh[krow][lcol]);
                unsigned bh1 = __float_as_uint(sxh[krow + 4][lcol]);
                unsigned bl0 = __float_as_uint(sxl[krow][lcol]);
                unsigned bl1 = __float_as_uint(sxl[krow + 4][lcol]);
                mma_tf32(accA[f][0], accA[f][1], accA[f][2], accA[f][3], ah[kc], bh0, bh1);
                mma_tf32(accB[f][0], accB[f][1], accB[f][2], accB[f][3], ah[kc], bl0, bl1);
                mma_tf32(accB[f][0], accB[f][1], accB[f][2], accB[f][3], al[kc], bh0, bh1);
            }
        }
    }

    int r0 = ct * 64 + mg * 16 + (lane >> 2);
#pragma unroll
    for (int f = 0; f < 4; f++) {
        int cb = ng * 32 + f * 8 + (lane & 3) * 2;
#pragma unroll
        for (int half = 0; half < 2; half++) {
            int n = r0 + half * 8;
            if (n >= Nout) continue;
            float bs = (b1 ? b1[n] : 0.f) + (b2 ? b2[n] : 0.f);
#pragma unroll
            for (int e = 0; e < 2; e++) {
                int bb = cb + e;
                float y = accA[f][half * 2 + e] + accB[f][half * 2 + e] + bs;
                if (c_mode == 0) {
                    if (act) y = fmaxf(y, 0.f);
                    C[(size_t)(m0 + bb) * Nout + n] = y;
                } else if (c_mode == 1)
                    C[(size_t)bb * Nout * 600 + (size_t)n * 600 + tb] = y;
                else
                    C[((size_t)tb * G4 + n) * 64 + bb] = y;
            }
        }
    }
}

// ---------------- counter grid barrier ----------------
__device__ __forceinline__ void wait_ctr(unsigned int* ctr, unsigned int target) {
    if (threadIdx.x == 0) {
        unsigned int cur;
        do {
            asm volatile("ld.acquire.gpu.u32 %0, [%1];" : "=r"(cur) : "l"(ctr) : "memory");
        } while (cur < target);
    }
    __syncthreads();
}
__device__ __forceinline__ void arrive_ctr(unsigned int* ctr) {
    __syncthreads();
    if (threadIdx.x == 0) { __threadfence(); atomicAdd(ctr, 1u); }
}

// ---------------- persistent LSTM recurrence ----------------
__device__ __forceinline__ void fill_chunk(float* stage, const float* __restrict__ wsrc,
                                           const float* __restrict__ hsrc, int tid) {
#pragma unroll
    for (int q = 0; q < 4; q++) {
        int v = q * 256 + tid;
        cpasync16(stage + v * 4, wsrc + (size_t)v * 4);
    }
#pragma unroll
    for (int q = 0; q < 8; q++) {
        int v = q * 256 + tid;
        int k = v >> 4, n4 = (v & 15) * 4;
        int sc = n4 ^ ((k & 3) * 8);
        cpasync16(stage + 4096 + k * 64 + sc, hsrc + (size_t)k * 64 + n4);
    }
}

__device__ __forceinline__ void prologue3(float* smem, const float* __restrict__ wpb,
                                          const float* __restrict__ hsrc, int tid) {
    fill_chunk(smem,             wpb,            hsrc,            tid); cp_commit();
    fill_chunk(smem + 12288,     wpb + 4096,     hsrc + 8192,     tid); cp_commit();
    fill_chunk(smem + 2 * 12288, wpb + 2 * 4096, hsrc + 2 * 8192, tid); cp_commit();
}

__device__ __forceinline__ void mma_loop8(float (*d)[4], float* smem,
                                          const float* __restrict__ wpb,
                                          const float* __restrict__ hsrc,
                                          int tid, int lane, int mg, const int colsw[2])
{
    for (int cl = 0; cl < 8; cl++) {
        cp_wait2();
        __syncthreads();
        if (cl + 3 < 8)
            fill_chunk(smem + ((cl + 3) & 3) * 12288, wpb + (size_t)(cl + 3) * 4096,
                       hsrc + (size_t)(cl + 3) * 8192, tid);
        cp_commit();
        const float* sA = smem + (cl & 3) * 12288;
        const unsigned* sHu = (const unsigned*)(sA + 4096);
#pragma unroll
        for (int s = 0; s < 4; s++) {
#pragma unroll
            for (int kc = 0; kc < 4; kc++) {
                uint4 a = *(const uint4*)(sA + s * 1024 + ((mg * 4 + kc) * 32 + lane) * 4);
                int kb = (s * 32 + kc * 8 + (lane & 3)) * 64;
#pragma unroll
                for (int f = 0; f < 2; f++) {
                    unsigned b0 = sHu[kb + colsw[f]];
                    unsigned b1 = sHu[kb + 256 + colsw[f]];
                    mma_tf32(d[f][0], d[f][1], d[f][2], d[f][3], a, b0, b1);
                }
            }
        }
    }
}

__device__ __forceinline__ void store_frags(float (*d)[4], float* gsum, int lane, int mg, int ng)
{
    int r0 = mg * 16 + (lane >> 2);
#pragma unroll
    for (int f = 0; f < 2; f++) {
        int cb = ng * 16 + f * 8 + (lane & 3) * 2;
        *(float2*)&gsum[r0 * 66 + cb]       = make_float2(d[f][0], d[f][1]);
        *(float2*)&gsum[(r0 + 8) * 66 + cb] = make_float2(d[f][2], d[f][3]);
    }
    __syncthreads();
}

__global__ __launch_bounds__(256, 1)
void lstm_persistent(const float* __restrict__ wp0, const float* __restrict__ wp1,
                     const float* __restrict__ bih1, const float* __restrict__ bhh1)
{
    extern __shared__ float smem[];
    float* sgx  = smem + 49152;
    float* gsum = smem + 51200;

    int tid = threadIdx.x;
    int lane = tid & 31, wid = tid >> 5;
    int mg = wid & 1, ng = wid >> 1;
    int bid = blockIdx.x;
    int jj0 = bid * 8;
    const float* wpb0 = wp0 + (size_t)bid * 32768;
    const float* wpb1 = wp1 + (size_t)bid * 65536;

    int colsw[2];
#pragma unroll
    for (int f = 0; f < 2; f++)
        colsw[f] = ((ng * 16 + f * 8) + (lane >> 2)) ^ ((lane & 3) * 8);

    float bsum[2][4];
#pragma unroll
    for (int e = 0; e < 2; e++) {
        int idx = e * 256 + tid;
        int jj = jj0 + (idx >> 6);
#pragma unroll
        for (int g = 0; g < 4; g++)
            bsum[e][g] = bih1[g * 1024 + jj] + bhh1[g * 1024 + jj];
    }

    float c0r[2] = {0.f, 0.f};
    float c1r[2] = {0.f, 0.f};
    unsigned int* ctrA = &g_ctrA[0];
    unsigned int* ctrB = &g_ctrB[0];

    // prologue for A(0)
    prologue3(smem, wpb0, g_ht0[0], tid);

    for (int t = 0; t < L_SEQ; t++) {
        const float* h0in = g_ht0[t & 1];
        float*       h0w  = g_ht0[(t + 1) & 1];
        const float* h1in = g_ht1[t & 1];
        float*       h1w  = g_ht1[(t + 1) & 1];

        // ======== phase A : layer 0 (prologue already in flight) ========
#pragma unroll
        for (int q = 0; q < 2; q++) {
            int v = q * 256 + tid;
            int g = v >> 7, rem = v & 127;
            const float* src = g_g0xT + ((size_t)t * 4096 + g * 1024 + jj0) * 64 + rem * 4;
            cpasync16(sgx + v * 4, src);
        }
        cp_commit();

        float dA[2][4];
#pragma unroll
        for (int f = 0; f < 2; f++)
#pragma unroll
            for (int r = 0; r < 4; r++) dA[f][r] = 0.f;
        mma_loop8(dA, smem, wpb0, h0in, tid, lane, mg, colsw);
        cp_wait0();
        store_frags(dA, gsum, lane, mg, ng);
#pragma unroll
        for (int e = 0; e < 2; e++) {
            int idx = e * 256 + tid;
            int b = idx & 63, jr = idx >> 6;
            int jj = jj0 + jr;
            float gi = gsum[jr * 66 + b]        + sgx[       jr * 64 + b];
            float gf = gsum[(8  + jr) * 66 + b] + sgx[512  + jr * 64 + b];
            float gg = gsum[(16 + jr) * 66 + b] + sgx[1024 + jr * 64 + b];
            float go = gsum[(24 + jr) * 66 + b] + sgx[1536 + jr * 64 + b];
            float cn = sigmoidf_(gf) * c0r[e] + sigmoidf_(gi) * tanhf(gg);
            float hn = sigmoidf_(go) * tanhf(cn);
            c0r[e] = cn;
            h0w[jj * 64 + b] = tf32r(hn);
        }
        arrive_ctr(ctrA);

        if (t > 0) wait_ctr(ctrB, (unsigned)(t * NBLK));

        // ======== phase B1 : Whh1 x h1(t-1) ========
        float dB[2][4];
#pragma unroll
        for (int f = 0; f < 2; f++)
#pragma unroll
            for (int r = 0; r < 4; r++) dB[f][r] = 0.f;
        prologue3(smem, wpb1 + (size_t)8 * 4096, h1in, tid);
        mma_loop8(dB, smem, wpb1 + (size_t)8 * 4096, h1in, tid, lane, mg, colsw);

        wait_ctr(ctrA, (unsigned)((t + 1) * NBLK));

        // ======== phase B2 : Wih1 x h0(t) ========
        prologue3(smem, wpb1, h0w, tid);
        mma_loop8(dB, smem, wpb1, h0w, tid, lane, mg, colsw);
        store_frags(dB, gsum, lane, mg, ng);

        // hoist A(t+1) prologue under cellB (inputs synced: waitA passed, wp0 static)
        if (t + 1 < L_SEQ)
            prologue3(smem, wpb0, g_ht0[(t + 1) & 1], tid);

#pragma unroll
        for (int e = 0; e < 2; e++) {
            int idx = e * 256 + tid;
            int b = idx & 63, jr = idx >> 6;
            int jj = jj0 + jr;
            float gi = gsum[jr * 66 + b]        + bsum[e][0];
            float gf = gsum[(8  + jr) * 66 + b] + bsum[e][1];
            float gg = gsum[(16 + jr) * 66 + b] + bsum[e][2];
            float go = gsum[(24 + jr) * 66 + b] + bsum[e][3];
            float cn = sigmoidf_(gf) * c1r[e] + sigmoidf_(gi) * tanhf(gg);
            float hn = sigmoidf_(go) * tanhf(cn);
            c1r[e] = cn;
            h1w[jj * 64 + b] = tf32r(hn);
            g_outs[((size_t)t * 1024 + jj) * 64 + b] = hn;
        }
        arrive_ctr(ctrB);
    }
}

// ---------------- conv1d via tf32 implicit GEMM (unchanged R11) ----------------
__global__ __launch_bounds__(256, 2)
void conv_mma(const float* __restrict__ x, const float* __restrict__ whi,
              const float* __restrict__ wlo, const float* __restrict__ bias,
              float* __restrict__ out, int Cin, int Cout, int chunks, int mode,
              const float* __restrict__ spred)
{
    __shared__ float4 spk[16 * 134];
    float* sp = (float*)spk;
    int b  = blockIdx.z;
    int ct = blockIdx.y;
    int l0 = blockIdx.x * 128;
    int tid = threadIdx.x;
    int lane = tid & 31, wid = tid >> 5;
    int mg = wid & 3, ng = wid >> 2;

    float accA[8][4], accB[8][4];
#pragma unroll
    for (int f = 0; f < 8; f++)
#pragma unroll
        for (int r = 0; r < 4; r++) { accA[f][r] = 0.f; accB[f][r] = 0.f; }

    const float* wh_base = whi + (size_t)ct * chunks * 5 * 2048 + (mg * 4) * 128 + lane * 4;
    const float* wl_base = wlo + (size_t)ct * chunks * 5 * 2048 + (mg * 4) * 128 + lane * 4;

    for (int c = 0; c < chunks; c++) {
        __syncthreads();
        for (int idx = tid; idx < 32 * 132; idx += 256) {
            int cil = idx / 132, lc = idx % 132;
            int gci = c * 32 + cil;
            int gl = l0 - 2 + lc;
            float v = (gci < Cin && gl >= 0 && gl < 600)
                      ? x[((size_t)b * Cin + gci) * 600 + gl] : 0.f;
            float h = tf32r(v);
            float l = tf32r(v - h);
            int kc = cil >> 3, rr = cil & 7;
            int row = kc * 4 + (rr & 3);
            int comp = rr >> 2;
            sp[(row * 134 + lc) * 4 + comp]     = h;
            sp[(row * 134 + lc) * 4 + comp + 2] = l;
        }
        __syncthreads();
#pragma unroll
        for (int tap = 0; tap < 5; tap++) {
            const float* whp = wh_base + (size_t)(c * 5 + tap) * 2048;
            const float* wlp = wl_base + (size_t)(c * 5 + tap) * 2048;
            uint4 ah[4], al[4];
#pragma unroll
            for (int kc = 0; kc < 4; kc++) {
                ah[kc] = *(const uint4*)(whp + kc * 128);
                al[kc] = *(const uint4*)(wlp + kc * 128);
            }
#pragma unroll
            for (int kc = 0; kc < 4; kc++) {
                int rbase = (kc * 4 + (lane & 3)) * 134;
#pragma unroll
                for (int f = 0; f < 8; f++) {
                    int lcol = ng * 64 + f * 8 + (lane >> 2) + tap;
                    float4 p = spk[rbase + lcol];
                    unsigned bh0 = __float_as_uint(p.x);
                    unsigned bh1 = __float_as_uint(p.y);
                    unsigned bl0 = __float_as_uint(p.z);
                    unsigned bl1 = __float_as_uint(p.w);
                    mma_tf32(accA[f][0], accA[f][1], accA[f][2], accA[f][3], ah[kc], bh0, bh1);
                    mma_tf32(accB[f][0], accB[f][1], accB[f][2], accB[f][3], ah[kc], bl0, bl1);
                    mma_tf32(accB[f][0], accB[f][1], accB[f][2], accB[f][3], al[kc], bh0, bh1);
                }
            }
        }
    }

    int r0 = ct * 64 + mg * 16 + (lane >> 2);
#pragma unroll
    for (int f = 0; f < 8; f++) {
        int lb = l0 + ng * 64 + f * 8 + (lane & 3) * 2;
#pragma unroll
        for (int half = 0; half < 2; half++) {
            int co = r0 + half * 8;
            if (co >= Cout) continue;
            float bs = bias[co];
#pragma unroll
            for (int e = 0; e < 2; e++) {
                int l = lb + e;
                if (l >= 600) continue;
                float y = accA[f][half * 2 + e] + accB[f][half * 2 + e] + bs;
                if (mode == 0) {
                    out[((size_t)b * Cout + co) * 600 + l] = tanhf(y);
                } else {
                    y += spred[((size_t)b * 552 + co) * 600 + l];
                    out[((size_t)l * 64 + b) * 552 + co] = y;
                }
            }
        }
    }
}

// ---------------- launcher ----------------
extern "C" void kernel_launch(void* const* d_in, const int* in_sizes, int n_in,
                              void* d_out, int out_size)
{
    const float* S_pad  = (const float*)d_in[0];
    const float* pre_W1 = (const float*)d_in[1];
    const float* pre_b1 = (const float*)d_in[2];
    const float* pre_W2 = (const float*)d_in[3];
    const float* pre_b2 = (const float*)d_in[4];
    const float* Wih0   = (const float*)d_in[5];
    const float* Whh0   = (const float*)d_in[6];
    const float* bih0   = (const float*)d_in[7];
    const float* bhh0   = (const float*)d_in[8];
    const float* Wih1   = (const float*)d_in[9];
    const float* Whh1   = (const float*)d_in[10];
    const float* bih1   = (const float*)d_in[11];
    const float* bhh1   = (const float*)d_in[12];
    const float* lin_W  = (const float*)d_in[13];
    const float* lin_b  = (const float*)d_in[14];
    const float* cw1 = (const float*)d_in[15];
    const float* cb1 = (const float*)d_in[16];
    const float* cw2 = (const float*)d_in[17];
    const float* cb2 = (const float*)d_in[18];
    const float* cw3 = (const float*)d_in[19];
    const float* cb3 = (const float*)d_in[20];
    const float* cw4 = (const float*)d_in[21];
    const float* cb4 = (const float*)d_in[22];
    const float* cw5 = (const float*)d_in[23];
    const float* cb5 = (const float*)d_in[24];

    float *pre1, *pre2, *g0xT, *wp0, *wp1, *cwhi, *cwlo, *outs, *spred, *cbA, *cbB;
    float *wg0hi, *wg0lo, *wlnhi, *wlnlo, *wp1hi, *wp1lo, *wp2hi, *wp2lo;
    cudaGetSymbolAddress((void**)&pre1, g_pre1);
    cudaGetSymbolAddress((void**)&pre2, g_pre2);
    cudaGetSymbolAddress((void**)&g0xT, g_g0xT);
    cudaGetSymbolAddress((void**)&wp0, g_wp0);
    cudaGetSymbolAddress((void**)&wp1, g_wp1);
    cudaGetSymbolAddress((void**)&cwhi, g_cwhi);
    cudaGetSymbolAddress((void**)&cwlo, g_cwlo);
    cudaGetSymbolAddress((void**)&wg0hi, g_wg0hi);
    cudaGetSymbolAddress((void**)&wg0lo, g_wg0lo);
    cudaGetSymbolAddress((void**)&wlnhi, g_wlnhi);
    cudaGetSymbolAddress((void**)&wlnlo, g_wlnlo);
    cudaGetSymbolAddress((void**)&wp1hi, g_wp1hi);
    cudaGetSymbolAddress((void**)&wp1lo, g_wp1lo);
    cudaGetSymbolAddress((void**)&wp2hi, g_wp2hi);
    cudaGetSymbolAddress((void**)&wp2lo, g_wp2lo);
    cudaGetSymbolAddress((void**)&outs, g_outs);
    cudaGetSymbolAddress((void**)&spred, g_spred);
    cudaGetSymbolAddress((void**)&cbA, g_cbA);
    cudaGetSymbolAddress((void**)&cbB, g_cbB);

    const int lstm_smem = 53312 * 4;  // 213248 bytes
    cudaFuncSetAttribute(lstm_persistent, cudaFuncAttributeMaxDynamicSharedMemorySize, lstm_smem);

    pack_w0_fused<<<4672, 1024>>>(Whh0, lin_W, wp0, wlnhi, wlnlo);
    pack_w1_fused<<<9216, 1024>>>(Wih1, Whh1, Wih0, wp1, wg0hi, wg0lo);
    pack_gemm<<<(GP_SZ_P1 + 255) / 256, 256>>>(pre_W1, wp1hi, wp1lo, DPRE, DSPEC, DSPEC, 18, GP_SZ_P1);
    pack_gemm<<<(GP_SZ_P2 + 255) / 256, 256>>>(pre_W2, wp2hi, wp2lo, DPRE, DPRE, DPRE, 8, GP_SZ_P2);

    // pre-net (tf32 3x, teacher-forcing shift + K guard, relu)
    gemm_tc<<<dim3(600, 4), 256>>>(S_pad, wp1hi, wp1lo, pre_b1, nullptr, pre1,
                                   DSPEC, 18, DPRE, 0, 0, 1, DSPEC, 1);
    gemm_tc<<<dim3(600, 4), 256>>>(pre1, wp2hi, wp2lo, pre_b2, nullptr, pre2,
                                   DPRE, 8, DPRE, 0, 0, 0, DPRE, 1);
    // layer-0 input gates (tf32 3x) -> [t][gate_row][b]
    gemm_tc<<<dim3(600, 64), 256>>>(pre2, wg0hi, wg0lo, bih0, bhh0, g0xT,
                                    DPRE, 8, G4, 0, 2, 0, DPRE, 0);
    // recurrence
    lstm_persistent<<<NBLK, 256, lstm_smem>>>(wp0, wp1, bih1, bhh1);

    // output linear (tf32 3x)
    gemm_tc<<<dim3(600, 9), 256>>>(outs, wlnhi, wlnlo, lin_b, nullptr, spred,
                                   DH, 32, DSPEC, 2, 1, 0, DH, 0);
    // conv packs
    pack_conv<<<(CP_SZ1 + 255) / 256, 256>>>(cw1, cwhi + CP_OFF1, cwlo + CP_OFF1, 512, 552, 18, CP_SZ1);
    pack_conv<<<(CP_SZ2 + 255) / 256, 256>>>(cw2, cwhi + CP_OFF2, cwlo + CP_OFF2, 512, 512, 16, CP_SZ2);
    pack_conv<<<(CP_SZ2 + 255) / 256, 256>>>(cw3, cwhi + CP_OFF3, cwlo + CP_OFF3, 512, 512, 16, CP_SZ2);
    pack_conv<<<(CP_SZ2 + 255) / 256, 256>>>(cw4, cwhi + CP_OFF4, cwlo + CP_OFF4, 512, 512, 16, CP_SZ2);
    pack_conv<<<(CP_SZ5 + 255) / 256, 256>>>(cw5, cwhi + CP_OFF5, cwlo + CP_OFF5, 552, 512, 16, CP_SZ5);
    // postnet
    conv_mma<<<dim3(5, 8, 64), 256>>>(spred, cwhi + CP_OFF1, cwlo + CP_OFF1, cb1, cbA, 552, 512, 18, 0, nullptr);
    conv_mma<<<dim3(5, 8, 64), 256>>>(cbA,   cwhi + CP_OFF2, cwlo + CP_OFF2, cb2, cbB, 512, 512, 16, 0, nullptr);
    conv_mma<<<dim3(5, 8, 64), 256>>>(cbB,   cwhi + CP_OFF3, cwlo + CP_OFF3, cb3, cbA, 512, 512, 16, 0, nullptr);
    conv_mma<<<dim3(5, 8, 64), 256>>>(cbA,   cwhi + CP_OFF4, cwlo + CP_OFF4, cb4, cbB, 512, 512, 16, 0, nullptr);
    conv_mma<<<dim3(5, 9, 64), 256>>>(cbB,   cwhi + CP_OFF5, cwlo + CP_OFF5, cb5, (float*)d_out, 512, 552, 16, 1, spred);
    (void)in_sizes; (void)n_in; (void)out_size;
}

// round 13
// speedup vs baseline: 1.0142x; 1.0142x over previous
#include <cuda_runtime.h>
#include <math.h>
#include <stdint.h>

#define L_SEQ   600
#define BATCH   64
#define DSPEC   552
#define DPRE    256
#define DH      1024
#define G4      4096
#define MROWS   (L_SEQ*BATCH)   // 38400
#define NBLK    128

// conv pack geometry
#define CP_SZ1  (8*18*5*2048)
#define CP_SZ2  (8*16*5*2048)
#define CP_SZ5  (9*16*5*2048)
#define CP_OFF1 0
#define CP_OFF2 (CP_OFF1 + CP_SZ1)
#define CP_OFF3 (CP_OFF2 + CP_SZ2)
#define CP_OFF4 (CP_OFF3 + CP_SZ2)
#define CP_OFF5 (CP_OFF4 + CP_SZ2)
#define CP_TOT  (CP_OFF5 + CP_SZ5)

// gemm_tc pack sizes
#define GP_SZ_W0 (64*8*2048)      // Wih0: N=4096, K=256
#define GP_SZ_LN (9*32*2048)      // lin_W: N=552, K=1024
#define GP_SZ_P1 (4*18*2048)      // pre_W1: N=256, K=552
#define GP_SZ_P2 (4*8*2048)       // pre_W2: N=256, K=256
#define WP0_SZ   (128*32*1024)
#define WP1_SZ   ((size_t)128*64*1024)

// ---------------- static device scratch ----------------
static __device__ float g_pre1 [(size_t)MROWS*DPRE];
static __device__ float g_pre2 [(size_t)MROWS*DPRE];
static __device__ float g_g0xT [(size_t)L_SEQ*G4*BATCH];     // [t][gate_row][b]
static __device__ float g_wp0  [(size_t)WP0_SZ];
static __device__ float g_wp1  [(size_t)WP1_SZ];
static __device__ float g_cwhi [(size_t)CP_TOT];
static __device__ float g_cwlo [(size_t)CP_TOT];
static __device__ float g_wg0hi[(size_t)GP_SZ_W0];
static __device__ float g_wg0lo[(size_t)GP_SZ_W0];
static __device__ float g_wlnhi[(size_t)GP_SZ_LN];
static __device__ float g_wlnlo[(size_t)GP_SZ_LN];
static __device__ float g_wp1hi[(size_t)GP_SZ_P1];
static __device__ float g_wp1lo[(size_t)GP_SZ_P1];
static __device__ float g_wp2hi[(size_t)GP_SZ_P2];
static __device__ float g_wp2lo[(size_t)GP_SZ_P2];
static __device__ float g_ht0  [2][DH*BATCH];
static __device__ float g_ht1  [2][DH*BATCH];
static __device__ float g_outs [(size_t)L_SEQ*DH*BATCH];     // [t][jj][b]
static __device__ float g_spred[(size_t)BATCH*DSPEC*L_SEQ];  // [B][552][600]
static __device__ float g_cbA  [(size_t)BATCH*DSPEC*L_SEQ];
static __device__ float g_cbB  [(size_t)BATCH*DSPEC*L_SEQ];
static __device__ unsigned int g_ctrA[32];
static __device__ unsigned int g_ctrB[32];

__device__ __forceinline__ float sigmoidf_(float x) { return 1.0f / (1.0f + expf(-x)); }

__device__ __forceinline__ float tf32r(float x) {
    unsigned u; asm("cvt.rna.tf32.f32 %0, %1;" : "=r"(u) : "f"(x));
    return __uint_as_float(u);
}

__device__ __forceinline__ void cpasync16(void* dst_smem, const void* src) {
    unsigned s = (unsigned)__cvta_generic_to_shared(dst_smem);
    asm volatile("cp.async.cg.shared.global [%0], [%1], 16;" :: "r"(s), "l"(src));
}
__device__ __forceinline__ void cp_commit() {
    asm volatile("cp.async.commit_group;" ::: "memory");
}
__device__ __forceinline__ void cp_wait2() {
    asm volatile("cp.async.wait_group 2;" ::: "memory");
}
__device__ __forceinline__ void cp_wait0() {
    asm volatile("cp.async.wait_group 0;" ::: "memory");
}

__device__ __forceinline__ void mma_tf32(float& d0, float& d1, float& d2, float& d3,
                                         uint4 a, unsigned b0, unsigned b1) {
    asm volatile(
        "mma.sync.aligned.m16n8k8.row.col.f32.tf32.tf32.f32 "
        "{%0,%1,%2,%3}, {%4,%5,%6,%7}, {%8,%9}, {%0,%1,%2,%3};"
        : "+f"(d0), "+f"(d1), "+f"(d2), "+f"(d3)
        : "r"(a.x), "r"(a.y), "r"(a.z), "r"(a.w), "r"(b0), "r"(b1));
}

// ---------------- gemm weight pack helper ----------------
__device__ __forceinline__ void pack_gemm_elem(const float* __restrict__ w,
                                               float* __restrict__ whi,
                                               float* __restrict__ wlo,
                                               int Nrows, int K, int wstride,
                                               int chunks, int i)
{
    int reg = i & 3, lane = (i >> 2) & 31, kc = (i >> 7) & 3, mh = (i >> 9) & 3;
    int rest = i >> 11;
    int c = rest % chunks;
    int ct = rest / chunks;
    int row16 = (lane >> 2) + (reg & 1) * 8;
    int col8  = (lane & 3) + ((reg >> 1) & 1) * 4;
    int n = ct * 64 + mh * 16 + row16;
    int k = c * 32 + kc * 8 + col8;
    float v = (n < Nrows && k < K) ? w[(size_t)n * wstride + k] : 0.f;
    float hi = tf32r(v);
    whi[i] = hi;
    wlo[i] = tf32r(v - hi);
}

__global__ void pack_gemm(const float* __restrict__ w, float* __restrict__ whi,
                          float* __restrict__ wlo, int Nrows, int K, int wstride,
                          int chunks, int elems)
{
    int i = blockIdx.x * blockDim.x + threadIdx.x;
    if (i < elems) pack_gemm_elem(w, whi, wlo, Nrows, K, wstride, chunks, i);
}

// ---------------- fused pack 1: wp0 + lin_W pack + init ----------------
__global__ void pack_w0_fused(const float* __restrict__ Whh0,
                              const float* __restrict__ lin_W,
                              float* __restrict__ wp,
                              float* __restrict__ wlnhi, float* __restrict__ wlnlo)
{
    size_t i = (size_t)blockIdx.x * blockDim.x + threadIdx.x;
    if (i < DH * BATCH) { g_ht0[0][i] = 0.f; g_ht1[0][i] = 0.f; }
    if (i == 0) { g_ctrA[0] = 0u; g_ctrB[0] = 0u; }

    if (i < (size_t)WP0_SZ) {
        int ii = (int)i;
        int reg = ii & 3, lane = (ii >> 2) & 31, kc = (ii >> 7) & 3, mh = (ii >> 9) & 1;
        int chunk = (ii >> 10) & 31, blk = ii >> 15;
        int row16 = (lane >> 2) + (reg & 1) * 8;
        int col8  = (lane & 3) + ((reg >> 1) & 1) * 4;
        int m = mh * 16 + row16;
        int j = (m >> 3) * 1024 + blk * 8 + (m & 7);
        int k = chunk * 32 + kc * 8 + col8;
        wp[ii] = tf32r(Whh0[(size_t)j * 1024 + k]);
    } else {
        int j = (int)(i - WP0_SZ);
        if (j < GP_SZ_LN)
            pack_gemm_elem(lin_W, wlnhi, wlnlo, DSPEC, DH, DH + 128, 32, j);
    }
}

// ---------------- fused pack 2: wp1 + Wih0 pack ----------------
__global__ void pack_w1_fused(const float* __restrict__ Wih1, const float* __restrict__ Whh1,
                              const float* __restrict__ Wih0,
                              float* __restrict__ wp,
                              float* __restrict__ wg0hi, float* __restrict__ wg0lo)
{
    size_t i = (size_t)blockIdx.x * blockDim.x + threadIdx.x;
    if (i < WP1_SZ) {
        int ii = (int)i;
        int reg = ii & 3, lane = (ii >> 2) & 31, kc = (ii >> 7) & 3, mh = (ii >> 9) & 1;
        int chunk = (ii >> 10) & 63, blk = ii >> 16;
        int row16 = (lane >> 2) + (reg & 1) * 8;
        int col8  = (lane & 3) + ((reg >> 1) & 1) * 4;
        int m = mh * 16 + row16;
        int j = (m >> 3) * 1024 + blk * 8 + (m & 7);
        int k = chunk * 32 + kc * 8 + col8;
        float v = (k < 1024) ? Wih1[(size_t)j * 1024 + k] : Whh1[(size_t)j * 1024 + (k - 1024)];
        wp[ii] = tf32r(v);
    } else {
        int j = (int)(i - WP1_SZ);
        if (j < GP_SZ_W0)
            pack_gemm_elem(Wih0, wg0hi, wg0lo, G4, DPRE, DPRE + 128, 8, j);
    }
}

// ---------------- conv weight pack ----------------
__global__ void pack_conv(const float* __restrict__ w, float* __restrict__ whi,
                          float* __restrict__ wlo, int Cout, int Cin, int chunks, int elems)
{
    int i = blockIdx.x * blockDim.x + threadIdx.x;
    if (i >= elems) return;
    int reg = i & 3, lane = (i >> 2) & 31, kc = (i >> 7) & 3, mh = (i >> 9) & 3;
    int rest = i >> 11;
    int tap = rest % 5; rest /= 5;
    int c = rest % chunks;
    int ct = rest / chunks;
    int row16 = (lane >> 2) + (reg & 1) * 8;
    int col8  = (lane & 3) + ((reg >> 1) & 1) * 4;
    int co = ct * 64 + mh * 16 + row16;
    int ci = c * 32 + kc * 8 + col8;
    float v = (co < Cout && ci < Cin) ? w[((size_t)co * Cin + ci) * 5 + tap] : 0.f;
    float hi = tf32r(v);
    whi[i] = hi;
    wlo[i] = tf32r(v - hi);
}

// ---------------- tf32 3x GEMM ----------------
// a_mode 0: A row-major [m][K], a_shift (teacher forcing) + Kvalid guard.
// a_mode 2: A = [t][k][64].
// c_mode 0: C[(m0+b)*Nout + n] (+relu if act); 1: [B][N][600]; 2: [t][4096][64].
__global__ __launch_bounds__(256, 2)
void gemm_tc(const float* __restrict__ A, const float* __restrict__ whi,
             const float* __restrict__ wlo, const float* __restrict__ b1,
             const float* __restrict__ b2, float* __restrict__ C,
             int K, int chunks, int Nout, int a_mode, int c_mode,
             int a_shift, int Kvalid, int act)
{
    __shared__ float sxh[32][72];
    __shared__ float sxl[32][72];
    int tb = blockIdx.x;
    int ct = blockIdx.y;
    int m0 = tb * 64;
    int tid = threadIdx.x;
    int lane = tid & 31, wid = tid >> 5;
    int mg = wid & 3, ng = wid >> 2;

    float accA[4][4], accB[4][4];
#pragma unroll
    for (int f = 0; f < 4; f++)
#pragma unroll
        for (int r = 0; r < 4; r++) { accA[f][r] = 0.f; accB[f][r] = 0.f; }

    const float* wh_base = whi + (size_t)ct * chunks * 2048 + (mg * 4) * 128 + lane * 4;
    const float* wl_base = wlo + (size_t)ct * chunks * 2048 + (mg * 4) * 128 + lane * 4;

    for (int c = 0; c < chunks; c++) {
        __syncthreads();
        if (a_mode == 0) {
#pragma unroll
            for (int q = 0; q < 2; q++) {
                int idx = q * 256 + tid;
                int m = idx >> 3, kq = idx & 7;
                int row = m0 + m - (a_shift ? 64 : 0);
                int gk = c * 32 + kq * 4;
                float4 v = make_float4(0.f, 0.f, 0.f, 0.f);
                if (row >= 0) {
                    const float* p = A + (size_t)row * K + gk;
                    if (gk + 4 <= Kvalid) v = *(const float4*)p;
                    else {
                        if (gk + 0 < Kvalid) v.x = p[0];
                        if (gk + 1 < Kvalid) v.y = p[1];
                        if (gk + 2 < Kvalid) v.z = p[2];
                        if (gk + 3 < Kvalid) v.w = p[3];
                    }
                }
                float h0 = tf32r(v.x), h1 = tf32r(v.y), h2 = tf32r(v.z), h3 = tf32r(v.w);
                sxh[kq*4+0][m] = h0; sxl[kq*4+0][m] = tf32r(v.x - h0);
                sxh[kq*4+1][m] = h1; sxl[kq*4+1][m] = tf32r(v.y - h1);
                sxh[kq*4+2][m] = h2; sxl[kq*4+2][m] = tf32r(v.z - h2);
                sxh[kq*4+3][m] = h3; sxl[kq*4+3][m] = tf32r(v.w - h3);
            }
        } else {
#pragma unroll
            for (int q = 0; q < 2; q++) {
                int idx = q * 256 + tid;
                int k = idx >> 4, m4 = (idx & 15) * 4;
                float4 v = *(const float4*)(A + ((size_t)tb * K + c * 32 + k) * 64 + m4);
                float h0 = tf32r(v.x), h1 = tf32r(v.y), h2 = tf32r(v.z), h3 = tf32r(v.w);
                sxh[k][m4+0] = h0; sxl[k][m4+0] = tf32r(v.x - h0);
                sxh[k][m4+1] = h1; sxl[k][m4+1] = tf32r(v.y - h1);
                sxh[k][m4+2] = h2; sxl[k][m4+2] = tf32r(v.z - h2);
                sxh[k][m4+3] = h3; sxl[k][m4+3] = tf32r(v.w - h3);
            }
        }
        __syncthreads();
        const float* whp = wh_base + (size_t)c * 2048;
        const float* wlp = wl_base + (size_t)c * 2048;
        uint4 ah[4], al[4];
#pragma unroll
        for (int kc = 0; kc < 4; kc++) {
            ah[kc] = *(const uint4*)(whp + kc * 128);
            al[kc] = *(const uint4*)(wlp + kc * 128);
        }
#pragma unroll
        for (int kc = 0; kc < 4; kc++) {
            int krow = kc * 8 + (lane & 3);
#pragma unroll
            for (int f = 0; f < 4; f++) {
                int lcol = ng * 32 + f * 8 + (lane >> 2);
                unsigned bh0 = __float_as_uint(sxh[krow][lcol]);
                unsigned bh1 = __float_as_uint(sxh[krow + 4][lcol]);
                unsigned bl0 = __float_as_uint(sxl[krow][lcol]);
                unsigned bl1 = __float_as_uint(sxl[krow + 4][lcol]);
                mma_tf32(accA[f][0], accA[f][1], accA[f][2], accA[f][3], ah[kc], bh0, bh1);
                mma_tf32(accB[f][0], accB[f][1], accB[f][2], accB[f][3], ah[kc], bl0, bl1);
                mma_tf32(accB[f][0], accB[f][1], accB[f][2], accB[f][3], al[kc], bh0, bh1);
            }
        }
    }

    int r0 = ct * 64 + mg * 16 + (lane >> 2);
#pragma unroll
    for (int f = 0; f < 4; f++) {
        int cb = ng * 32 + f * 8 + (lane & 3) * 2;
#pragma unroll
        for (int half = 0; half < 2; half++) {
            int n = r0 + half * 8;
            if (n >= Nout) continue;
            float bs = (b1 ? b1[n] : 0.f) + (b2 ? b2[n] : 0.f);
#pragma unroll
            for (int e = 0; e < 2; e++) {
                int bb = cb + e;
                float y = accA[f][half * 2 + e] + accB[f][half * 2 + e] + bs;
                if (c_mode == 0) {
                    if (act) y = fmaxf(y, 0.f);
                    C[(size_t)(m0 + bb) * Nout + n] = y;
                } else if (c_mode == 1)
                    C[(size_t)bb * Nout * 600 + (size_t)n * 600 + tb] = y;
                else
                    C[((size_t)tb * G4 + n) * 64 + bb] = y;
            }
        }
    }
}

// ---------------- counter grid barrier ----------------
__device__ __forceinline__ void wait_ctr(unsigned int* ctr, unsigned int target) {
    if (threadIdx.x == 0) {
        unsigned int cur;
        do {
            asm volatile("ld.acquire.gpu.u32 %0, [%1];" : "=r"(cur) : "l"(ctr) : "memory");
        } while (cur < target);
    }
    __syncthreads();
}
__device__ __forceinline__ void arrive_ctr(unsigned int* ctr) {
    __syncthreads();
    if (threadIdx.x == 0) { __threadfence(); atomicAdd(ctr, 1u); }
}

// ---------------- persistent LSTM recurrence (R11 config, unchanged) ----------------
__device__ __forceinline__ void fill_chunk(float* stage, const float* __restrict__ wsrc,
                                           const float* __restrict__ hsrc, int tid) {
#pragma unroll
    for (int q = 0; q < 4; q++) {
        int v = q * 256 + tid;
        cpasync16(stage + v * 4, wsrc + (size_t)v * 4);
    }
#pragma unroll
    for (int q = 0; q < 8; q++) {
        int v = q * 256 + tid;
        int k = v >> 4, n4 = (v & 15) * 4;
        int sc = n4 ^ ((k & 3) * 8);
        cpasync16(stage + 4096 + k * 64 + sc, hsrc + (size_t)k * 64 + n4);
    }
}

__device__ __forceinline__ void mma_sub8(float (*d)[4], float* smem,
                                         const float* __restrict__ wpb,
                                         const float* __restrict__ hsrc,
                                         int tid, int lane, int mg, const int colsw[2])
{
    fill_chunk(smem,             wpb,                 hsrc,                 tid); cp_commit();
    fill_chunk(smem + 12288,     wpb + 4096,          hsrc + 8192,          tid); cp_commit();
    fill_chunk(smem + 2 * 12288, wpb + 2 * 4096,      hsrc + 2 * 8192,      tid); cp_commit();
    for (int cl = 0; cl < 8; cl++) {
        cp_wait2();
        __syncthreads();
        if (cl + 3 < 8)
            fill_chunk(smem + ((cl + 3) & 3) * 12288, wpb + (size_t)(cl + 3) * 4096,
                       hsrc + (size_t)(cl + 3) * 8192, tid);
        cp_commit();
        const float* sA = smem + (cl & 3) * 12288;
        const unsigned* sHu = (const unsigned*)(sA + 4096);
#pragma unroll
        for (int s = 0; s < 4; s++) {
#pragma unroll
            for (int kc = 0; kc < 4; kc++) {
                uint4 a = *(const uint4*)(sA + s * 1024 + ((mg * 4 + kc) * 32 + lane) * 4);
                int kb = (s * 32 + kc * 8 + (lane & 3)) * 64;
#pragma unroll
                for (int f = 0; f < 2; f++) {
                    unsigned b0 = sHu[kb + colsw[f]];
                    unsigned b1 = sHu[kb + 256 + colsw[f]];
                    mma_tf32(d[f][0], d[f][1], d[f][2], d[f][3], a, b0, b1);
                }
            }
        }
    }
}

__device__ __forceinline__ void store_frags(float (*d)[4], float* gsum, int lane, int mg, int ng)
{
    int r0 = mg * 16 + (lane >> 2);
#pragma unroll
    for (int f = 0; f < 2; f++) {
        int cb = ng * 16 + f * 8 + (lane & 3) * 2;
        *(float2*)&gsum[r0 * 66 + cb]       = make_float2(d[f][0], d[f][1]);
        *(float2*)&gsum[(r0 + 8) * 66 + cb] = make_float2(d[f][2], d[f][3]);
    }
    __syncthreads();
}

__global__ __launch_bounds__(256, 1)
void lstm_persistent(const float* __restrict__ wp0, const float* __restrict__ wp1,
                     const float* __restrict__ bih1, const float* __restrict__ bhh1)
{
    extern __shared__ float smem[];
    float* sgx  = smem + 49152;
    float* gsum = smem + 51200;

    int tid = threadIdx.x;
    int lane = tid & 31, wid = tid >> 5;
    int mg = wid & 1, ng = wid >> 1;
    int bid = blockIdx.x;
    int jj0 = bid * 8;
    const float* wpb0 = wp0 + (size_t)bid * 32768;
    const float* wpb1 = wp1 + (size_t)bid * 65536;

    int colsw[2];
#pragma unroll
    for (int f = 0; f < 2; f++)
        colsw[f] = ((ng * 16 + f * 8) + (lane >> 2)) ^ ((lane & 3) * 8);

    float bsum[2][4];
#pragma unroll
    for (int e = 0; e < 2; e++) {
        int idx = e * 256 + tid;
        int jj = jj0 + (idx >> 6);
#pragma unroll
        for (int g = 0; g < 4; g++)
            bsum[e][g] = bih1[g * 1024 + jj] + bhh1[g * 1024 + jj];
    }

    float c0r[2] = {0.f, 0.f};
    float c1r[2] = {0.f, 0.f};
    unsigned int* ctrA = &g_ctrA[0];
    unsigned int* ctrB = &g_ctrB[0];

    for (int t = 0; t < L_SEQ; t++) {
        const float* h0in = g_ht0[t & 1];
        float*       h0w  = g_ht0[(t + 1) & 1];
        const float* h1in = g_ht1[t & 1];
        float*       h1w  = g_ht1[(t + 1) & 1];

        // ======== phase A : layer 0 ========
#pragma unroll
        for (int q = 0; q < 2; q++) {
            int v = q * 256 + tid;
            int g = v >> 7, rem = v & 127;
            const float* src = g_g0xT + ((size_t)t * 4096 + g * 1024 + jj0) * 64 + rem * 4;
            cpasync16(sgx + v * 4, src);
        }
        cp_commit();

        float dA[2][4];
#pragma unroll
        for (int f = 0; f < 2; f++)
#pragma unroll
            for (int r = 0; r < 4; r++) dA[f][r] = 0.f;
        mma_sub8(dA, smem, wpb0, h0in, tid, lane, mg, colsw);
        cp_wait0();
        store_frags(dA, gsum, lane, mg, ng);
#pragma unroll
        for (int e = 0; e < 2; e++) {
            int idx = e * 256 + tid;
            int b = idx & 63, jr = idx >> 6;
            int jj = jj0 + jr;
            float gi = gsum[jr * 66 + b]        + sgx[       jr * 64 + b];
            float gf = gsum[(8  + jr) * 66 + b] + sgx[512  + jr * 64 + b];
            float gg = gsum[(16 + jr) * 66 + b] + sgx[1024 + jr * 64 + b];
            float go = gsum[(24 + jr) * 66 + b] + sgx[1536 + jr * 64 + b];
            float cn = sigmoidf_(gf) * c0r[e] + sigmoidf_(gi) * tanhf(gg);
            float hn = sigmoidf_(go) * tanhf(cn);
            c0r[e] = cn;
            h0w[jj * 64 + b] = tf32r(hn);
        }
        arrive_ctr(ctrA);

        if (t > 0) wait_ctr(ctrB, (unsigned)(t * NBLK));

        // ======== phase B1 : Whh1 x h1(t-1) ========
        float dB[2][4];
#pragma unroll
        for (int f = 0; f < 2; f++)
#pragma unroll
            for (int r = 0; r < 4; r++) dB[f][r] = 0.f;
        mma_sub8(dB, smem, wpb1 + (size_t)8 * 4096, h1in, tid, lane, mg, colsw);

        wait_ctr(ctrA, (unsigned)((t + 1) * NBLK));

        // ======== phase B2 : Wih1 x h0(t) ========
        mma_sub8(dB, smem, wpb1, h0w, tid, lane, mg, colsw);
        store_frags(dB, gsum, lane, mg, ng);
#pragma unroll
        for (int e = 0; e < 2; e++) {
            int idx = e * 256 + tid;
            int b = idx & 63, jr = idx >> 6;
            int jj = jj0 + jr;
            float gi = gsum[jr * 66 + b]        + bsum[e][0];
            float gf = gsum[(8  + jr) * 66 + b] + bsum[e][1];
            float gg = gsum[(16 + jr) * 66 + b] + bsum[e][2];
            float go = gsum[(24 + jr) * 66 + b] + bsum[e][3];
            float cn = sigmoidf_(gf) * c1r[e] + sigmoidf_(gi) * tanhf(gg);
            float hn = sigmoidf_(go) * tanhf(cn);
            c1r[e] = cn;
            h1w[jj * 64 + b] = tf32r(hn);
            g_outs[((size_t)t * 1024 + jj) * 64 + b] = hn;
        }
        arrive_ctr(ctrB);
    }
}

// ---------------- conv1d via tf32 implicit GEMM (R11, unchanged) ----------------
__global__ __launch_bounds__(256, 2)
void conv_mma(const float* __restrict__ x, const float* __restrict__ whi,
              const float* __restrict__ wlo, const float* __restrict__ bias,
              float* __restrict__ out, int Cin, int Cout, int chunks, int mode,
              const float* __restrict__ spred)
{
    __shared__ float4 spk[16 * 134];
    float* sp = (float*)spk;
    int b  = blockIdx.z;
    int ct = blockIdx.y;
    int l0 = blockIdx.x * 128;
    int tid = threadIdx.x;
    int lane = tid & 31, wid = tid >> 5;
    int mg = wid & 3, ng = wid >> 2;

    float accA[8][4], accB[8][4];
#pragma unroll
    for (int f = 0; f < 8; f++)
#pragma unroll
        for (int r = 0; r < 4; r++) { accA[f][r] = 0.f; accB[f][r] = 0.f; }

    const float* wh_base = whi + (size_t)ct * chunks * 5 * 2048 + (mg * 4) * 128 + lane * 4;
    const float* wl_base = wlo + (size_t)ct * chunks * 5 * 2048 + (mg * 4) * 128 + lane * 4;

    for (int c = 0; c < chunks; c++) {
        __syncthreads();
        for (int idx = tid; idx < 32 * 132; idx += 256) {
            int cil = idx / 132, lc = idx % 132;
            int gci = c * 32 + cil;
            int gl = l0 - 2 + lc;
            float v = (gci < Cin && gl >= 0 && gl < 600)
                      ? x[((size_t)b * Cin + gci) * 600 + gl] : 0.f;
            float h = tf32r(v);
            float l = tf32r(v - h);
            int kc = cil >> 3, rr = cil & 7;
            int row = kc * 4 + (rr & 3);
            int comp = rr >> 2;
            sp[(row * 134 + lc) * 4 + comp]     = h;
            sp[(row * 134 + lc) * 4 + comp + 2] = l;
        }
        __syncthreads();
#pragma unroll
        for (int tap = 0; tap < 5; tap++) {
            const float* whp = wh_base + (size_t)(c * 5 + tap) * 2048;
            const float* wlp = wl_base + (size_t)(c * 5 + tap) * 2048;
            uint4 ah[4], al[4];
#pragma unroll
            for (int kc = 0; kc < 4; kc++) {
                ah[kc] = *(const uint4*)(whp + kc * 128);
                al[kc] = *(const uint4*)(wlp + kc * 128);
            }
#pragma unroll
            for (int kc = 0; kc < 4; kc++) {
                int rbase = (kc * 4 + (lane & 3)) * 134;
#pragma unroll
                for (int f = 0; f < 8; f++) {
                    int lcol = ng * 64 + f * 8 + (lane >> 2) + tap;
                    float4 p = spk[rbase + lcol];
                    unsigned bh0 = __float_as_uint(p.x);
                    unsigned bh1 = __float_as_uint(p.y);
                    unsigned bl0 = __float_as_uint(p.z);
                    unsigned bl1 = __float_as_uint(p.w);
                    mma_tf32(accA[f][0], accA[f][1], accA[f][2], accA[f][3], ah[kc], bh0, bh1);
                    mma_tf32(accB[f][0], accB[f][1], accB[f][2], accB[f][3], ah[kc], bl0, bl1);
                    mma_tf32(accB[f][0], accB[f][1], accB[f][2], accB[f][3], al[kc], bh0, bh1);
                }
            }
        }
    }

    int r0 = ct * 64 + mg * 16 + (lane >> 2);
#pragma unroll
    for (int f = 0; f < 8; f++) {
        int lb = l0 + ng * 64 + f * 8 + (lane & 3) * 2;
#pragma unroll
        for (int half = 0; half < 2; half++) {
            int co = r0 + half * 8;
            if (co >= Cout) continue;
            float bs = bias[co];
#pragma unroll
            for (int e = 0; e < 2; e++) {
                int l = lb + e;
                if (l >= 600) continue;
                float y = accA[f][half * 2 + e] + accB[f][half * 2 + e] + bs;
                if (mode == 0) {
                    out[((size_t)b * Cout + co) * 600 + l] = tanhf(y);
                } else {
                    y += spred[((size_t)b * 552 + co) * 600 + l];
                    out[((size_t)l * 64 + b) * 552 + co] = y;
                }
            }
        }
    }
}

// ---------------- launcher ----------------
extern "C" void kernel_launch(void* const* d_in, const int* in_sizes, int n_in,
                              void* d_out, int out_size)
{
    const float* S_pad  = (const float*)d_in[0];
    const float* pre_W1 = (const float*)d_in[1];
    const float* pre_b1 = (const float*)d_in[2];
    const float* pre_W2 = (const float*)d_in[3];
    const float* pre_b2 = (const float*)d_in[4];
    const float* Wih0   = (const float*)d_in[5];
    const float* Whh0   = (const float*)d_in[6];
    const float* bih0   = (const float*)d_in[7];
    const float* bhh0   = (const float*)d_in[8];
    const float* Wih1   = (const float*)d_in[9];
    const float* Whh1   = (const float*)d_in[10];
    const float* bih1   = (const float*)d_in[11];
    const float* bhh1   = (const float*)d_in[12];
    const float* lin_W  = (const float*)d_in[13];
    const float* lin_b  = (const float*)d_in[14];
    const float* cw1 = (const float*)d_in[15];
    const float* cb1 = (const float*)d_in[16];
    const float* cw2 = (const float*)d_in[17];
    const float* cb2 = (const float*)d_in[18];
    const float* cw3 = (const float*)d_in[19];
    const float* cb3 = (const float*)d_in[20];
    const float* cw4 = (const float*)d_in[21];
    const float* cb4 = (const float*)d_in[22];
    const float* cw5 = (const float*)d_in[23];
    const float* cb5 = (const float*)d_in[24];

    float *pre1, *pre2, *g0xT, *wp0, *wp1, *cwhi, *cwlo, *outs, *spred, *cbA, *cbB;
    float *wg0hi, *wg0lo, *wlnhi, *wlnlo, *wp1hi, *wp1lo, *wp2hi, *wp2lo;
    cudaGetSymbolAddress((void**)&pre1, g_pre1);
    cudaGetSymbolAddress((void**)&pre2, g_pre2);
    cudaGetSymbolAddress((void**)&g0xT, g_g0xT);
    cudaGetSymbolAddress((void**)&wp0, g_wp0);
    cudaGetSymbolAddress((void**)&wp1, g_wp1);
    cudaGetSymbolAddress((void**)&cwhi, g_cwhi);
    cudaGetSymbolAddress((void**)&cwlo, g_cwlo);
    cudaGetSymbolAddress((void**)&wg0hi, g_wg0hi);
    cudaGetSymbolAddress((void**)&wg0lo, g_wg0lo);
    cudaGetSymbolAddress((void**)&wlnhi, g_wlnhi);
    cudaGetSymbolAddress((void**)&wlnlo, g_wlnlo);
    cudaGetSymbolAddress((void**)&wp1hi, g_wp1hi);
    cudaGetSymbolAddress((void**)&wp1lo, g_wp1lo);
    cudaGetSymbolAddress((void**)&wp2hi, g_wp2hi);
    cudaGetSymbolAddress((void**)&wp2lo, g_wp2lo);
    cudaGetSymbolAddress((void**)&outs, g_outs);
    cudaGetSymbolAddress((void**)&spred, g_spred);
    cudaGetSymbolAddress((void**)&cbA, g_cbA);
    cudaGetSymbolAddress((void**)&cbB, g_cbB);

    const int lstm_smem = 53312 * 4;  // 213248 bytes
    cudaFuncSetAttribute(lstm_persistent, cudaFuncAttributeMaxDynamicSharedMemorySize, lstm_smem);

    pack_w0_fused<<<4672, 1024>>>(Whh0, lin_W, wp0, wlnhi, wlnlo);
    pack_w1_fused<<<9216, 1024>>>(Wih1, Whh1, Wih0, wp1, wg0hi, wg0lo);
    pack_gemm<<<(GP_SZ_P1 + 255) / 256, 256>>>(pre_W1, wp1hi, wp1lo, DPRE, DSPEC, DSPEC, 18, GP_SZ_P1);
    pack_gemm<<<(GP_SZ_P2 + 255) / 256, 256>>>(pre_W2, wp2hi, wp2lo, DPRE, DPRE, DPRE, 8, GP_SZ_P2);

    // pre-net (tf32 3x)
    gemm_tc<<<dim3(600, 4), 256>>>(S_pad, wp1hi, wp1lo, pre_b1, nullptr, pre1,
                                   DSPEC, 18, DPRE, 0, 0, 1, DSPEC, 1);
    gemm_tc<<<dim3(600, 4), 256>>>(pre1, wp2hi, wp2lo, pre_b2, nullptr, pre2,
                                   DPRE, 8, DPRE, 0, 0, 0, DPRE, 1);
    // layer-0 input gates (tf32 3x) -> [t][gate_row][b]
    gemm_tc<<<dim3(600, 64), 256>>>(pre2, wg0hi, wg0lo, bih0, bhh0, g0xT,
                                    DPRE, 8, G4, 0, 2, 0, DPRE, 0);
    // recurrence (R11 config)
    lstm_persistent<<<NBLK, 256, lstm_smem>>>(wp0, wp1, bih1, bhh1);

    // output linear (tf32 3x)
    gemm_tc<<<dim3(600, 9), 256>>>(outs, wlnhi, wlnlo, lin_b, nullptr, spred,
                                   DH, 32, DSPEC, 2, 1, 0, DH, 0);
    // conv packs
    pack_conv<<<(CP_SZ1 + 255) / 256, 256>>>(cw1, cwhi + CP_OFF1, cwlo + CP_OFF1, 512, 552, 18, CP_SZ1);
    pack_conv<<<(CP_SZ2 + 255) / 256, 256>>>(cw2, cwhi + CP_OFF2, cwlo + CP_OFF2, 512, 512, 16, CP_SZ2);
    pack_conv<<<(CP_SZ2 + 255) / 256, 256>>>(cw3, cwhi + CP_OFF3, cwlo + CP_OFF3, 512, 512, 16, CP_SZ2);
    pack_conv<<<(CP_SZ2 + 255) / 256, 256>>>(cw4, cwhi + CP_OFF4, cwlo + CP_OFF4, 512, 512, 16, CP_SZ2);
    pack_conv<<<(CP_SZ5 + 255) / 256, 256>>>(cw5, cwhi + CP_OFF5, cwlo + CP_OFF5, 552, 512, 16, CP_SZ5);
    // postnet
    conv_mma<<<dim3(5, 8, 64), 256>>>(spred, cwhi + CP_OFF1, cwlo + CP_OFF1, cb1, cbA, 552, 512, 18, 0, nullptr);
    conv_mma<<<dim3(5, 8, 64), 256>>>(cbA,   cwhi + CP_OFF2, cwlo + CP_OFF2, cb2, cbB, 512, 512, 16, 0, nullptr);
    conv_mma<<<dim3(5, 8, 64), 256>>>(cbB,   cwhi + CP_OFF3, cwlo + CP_OFF3, cb3, cbA, 512, 512, 16, 0, nullptr);
    conv_mma<<<dim3(5, 8, 64), 256>>>(cbA,   cwhi + CP_OFF4, cwlo + CP_OFF4, cb4, cbB, 512, 512, 16, 0, nullptr);
    conv_mma<<<dim3(5, 9, 64), 256>>>(cbB,   cwhi + CP_OFF5, cwlo + CP_OFF5, cb5, (float*)d_out, 512, 552, 16, 1, spred);
    (void)in_sizes; (void)n_in; (void)out_size;
}